// round 13
// baseline (speedup 1.0000x reference)
#include <cuda_runtime.h>
#include <cuda_bf16.h>
#include <cstddef>
#include <cstdint>

#define N_NODE 10000
#define N_INST 50000
#define N_SVC  20000
#define NEDGE  200000
#define D      128
#define NREL   6
#define MAXN   50000
#define TOTAL_DST_ROWS 200000
#define CAP 128
#define TILE_ELEMS 16384         // 128x128 bf16 elements per tile (32 KB)
#define NTILE 1566               // sc:157 in:79 ni:391 ii:391 si:391 is:157
#define GATHER_BLOCKS (NTILE * 16)
// Tile bases: sc=0, in=157, ni=236, ii=627, si=1018, is=1409

// Static scratch.
__device__ int   g_bucket[(size_t)TOTAL_DST_ROWS * CAP];   // ~102 MB
__device__ int   g_cnt[TOTAL_DST_ROWS];
__device__ int   g_outdeg[NREL * MAXN];
__device__ __nv_bfloat16 g_Ahi[(size_t)NTILE * TILE_ELEMS]; // 51.3 MB
__device__ __nv_bfloat16 g_Alo[(size_t)NTILE * TILE_ELEMS]; // 51.3 MB
__device__ __nv_bfloat16 g_Bhi[NREL * TILE_ELEMS];
__device__ __nv_bfloat16 g_Blo[NREL * TILE_ELEMS];

// ---------------------------------------------------------------------------
__device__ __forceinline__ uint32_t smem_u32(const void* p) {
    uint32_t a;
    asm("{ .reg .u64 t; cvta.to.shared.u64 t, %1; cvt.u32.u64 %0, t; }"
        : "=r"(a) : "l"(p));
    return a;
}

// ldmatrix XOR swizzle: 256 B/row; 16B chunk id XORed with (row&7) in low 3 bits.
__device__ __forceinline__ uint32_t swz_off(int r, int chunk) {
    return (uint32_t)(r * 256 + (((chunk & 8) | ((chunk ^ (r & 7)) & 7)) << 4));
}

#define LDSM_X4(r0, r1, r2, r3, addr) \
    asm volatile("ldmatrix.sync.aligned.m8n8.x4.shared.b16 {%0,%1,%2,%3}, [%4];" \
                 : "=r"(r0), "=r"(r1), "=r"(r2), "=r"(r3) : "r"(addr))

__device__ __forceinline__ void mma16816(float* c, const uint32_t* a, const uint32_t* b) {
    asm volatile("mma.sync.aligned.m16n8k16.row.col.f32.bf16.bf16.f32 "
                 "{%0,%1,%2,%3}, {%4,%5,%6,%7}, {%8,%9}, {%0,%1,%2,%3};"
                 : "+f"(c[0]), "+f"(c[1]), "+f"(c[2]), "+f"(c[3])
                 : "r"(a[0]), "r"(a[1]), "r"(a[2]), "r"(a[3]),
                   "r"(b[0]), "r"(b[1]));
}

#define CP_ASYNC16(sm, g) \
    asm volatile("cp.async.cg.shared.global [%0], [%1], 16;" :: "r"(sm), "l"(g))
#define CP_COMMIT() asm volatile("cp.async.commit_group;" ::: "memory")
#define CP_WAIT0()  asm volatile("cp.async.wait_group 0;" ::: "memory")
#define CP_WAIT1()  asm volatile("cp.async.wait_group 1;" ::: "memory")

// ---------------------------------------------------------------------------
__global__ void zero_counts_kernel() {
    int i = blockIdx.x * blockDim.x + threadIdx.x;
    int stride = gridDim.x * blockDim.x;
    for (int j = i; j < TOTAL_DST_ROWS; j += stride) g_cnt[j] = 0;
    for (int j = i; j < NREL * MAXN; j += stride) g_outdeg[j] = 0;
}

// ---------------------------------------------------------------------------
__global__ void build_kernel(const int* __restrict__ s0, const int* __restrict__ d0,
                             const int* __restrict__ s1, const int* __restrict__ d1,
                             const int* __restrict__ s2, const int* __restrict__ d2,
                             const int* __restrict__ s3, const int* __restrict__ d3,
                             const int* __restrict__ s4, const int* __restrict__ d4,
                             const int* __restrict__ s5, const int* __restrict__ d5) {
    int i = blockIdx.x * blockDim.x + threadIdx.x;
    if (i >= NREL * NEDGE) return;
    int rel = i / NEDGE;
    int e = i - rel * NEDGE;
    const int* sp; const int* dp; int off;
    switch (rel) {
        case 0: sp = s0; dp = d0; off = 0;      break;
        case 1: sp = s1; dp = d1; off = 20000;  break;
        case 2: sp = s2; dp = d2; off = 30000;  break;
        case 3: sp = s3; dp = d3; off = 80000;  break;
        case 4: sp = s4; dp = d4; off = 130000; break;
        default: sp = s5; dp = d5; off = 180000; break;
    }
    int s = sp[e];
    int d = dp[e];
    atomicAdd(&g_outdeg[rel * MAXN + s], 1);
    int pos = atomicAdd(&g_cnt[off + d], 1);
    if (pos < CAP) g_bucket[(size_t)(off + d) * CAP + pos] = s;
}

// ---------------------------------------------------------------------------
// Gather (+ folded W prep): blocks < GATHER_BLOCKS do warp-per-row gather into
// split-bf16 swizzled tiles; the 6 extra blocks split W into K-major tiles.
__global__ void gather_all_kernel(const float* __restrict__ X0,  // svc  (sc)
                                  const float* __restrict__ X1,  // inst (in)
                                  const float* __restrict__ X2,  // node (ni)
                                  const float* __restrict__ X3,  // inst (ii)
                                  const float* __restrict__ X4,  // svc  (si)
                                  const float* __restrict__ X5,  // inst (is)
                                  const float* __restrict__ W0,
                                  const float* __restrict__ W1,
                                  const float* __restrict__ W2,
                                  const float* __restrict__ W3,
                                  const float* __restrict__ W4,
                                  const float* __restrict__ W5)
{
    if (blockIdx.x >= GATHER_BLOCKS) {
        // ---- W prep ----
        int rel = blockIdx.x - GATHER_BLOCKS;
        const float* W;
        switch (rel) {
            case 0: W = W0; break; case 1: W = W1; break; case 2: W = W2; break;
            case 3: W = W3; break; case 4: W = W4; break; default: W = W5; break;
        }
        char* bh = (char*)(g_Bhi + (size_t)rel * TILE_ELEMS);
        char* bl = (char*)(g_Blo + (size_t)rel * TILE_ELEMS);
        for (int idx = threadIdx.x; idx < D * D; idx += blockDim.x) {
            int k = idx >> 7, n = idx & 127;       // W[k][n] -> B[n][k]
            float v = W[idx];
            __nv_bfloat16 h = __float2bfloat16(v);
            __nv_bfloat16 l = __float2bfloat16(v - __bfloat162float(h));
            uint32_t p = swz_off(n, k >> 3) + (uint32_t)((k & 7) * 2);
            *(__nv_bfloat16*)(bh + p) = h;
            *(__nv_bfloat16*)(bl + p) = l;
        }
        return;
    }

    int gw = (blockIdx.x * blockDim.x + threadIdx.x) >> 5;   // padded row id
    int lane = threadIdx.x & 31;
    int tile = gw >> 7;

    int rel, pbase, segN, tbase; const float* X; float scale;
    if      (tile < 157)  { rel = 0; X = X0; scale = 0.5f;      pbase = 0;      segN = 20000; tbase = 0; }
    else if (tile < 236)  { rel = 1; X = X1; scale = 1.0f;      pbase = 20000;  segN = 10000; tbase = 157; }
    else if (tile < 627)  { rel = 2; X = X2; scale = 1.f / 3.f; pbase = 30000;  segN = 50000; tbase = 236; }
    else if (tile < 1018) { rel = 3; X = X3; scale = 1.f / 3.f; pbase = 80000;  segN = 50000; tbase = 627; }
    else if (tile < 1409) { rel = 4; X = X4; scale = 1.f / 3.f; pbase = 130000; segN = 50000; tbase = 1018; }
    else                  { rel = 5; X = X5; scale = 0.5f;      pbase = 180000; segN = 20000; tbase = 1409; }

    int local = gw - (tbase << 7);
    float4 acc0 = make_float4(0.f, 0.f, 0.f, 0.f);
    float4 acc1 = make_float4(0.f, 0.f, 0.f, 0.f);
    if (local < segN) {
        int g = pbase + local;
        int cnt = g_cnt[g];
        int deg = cnt < CAP ? cnt : CAP;
        const int* bk = g_bucket + (size_t)g * CAP;
        const int* od = g_outdeg + rel * MAXN;
        const float4* Xv = (const float4*)X;
        int j = 0;
        for (; j + 2 <= deg; j += 2) {
            int s0 = bk[j], s1 = bk[j + 1];
            float rs0 = rsqrtf(fmaxf((float)od[s0], 1.f));
            float rs1 = rsqrtf(fmaxf((float)od[s1], 1.f));
            float4 v0 = Xv[(size_t)s0 * 32 + lane];
            float4 v1 = Xv[(size_t)s1 * 32 + lane];
            acc0.x = fmaf(v0.x, rs0, acc0.x);
            acc0.y = fmaf(v0.y, rs0, acc0.y);
            acc0.z = fmaf(v0.z, rs0, acc0.z);
            acc0.w = fmaf(v0.w, rs0, acc0.w);
            acc1.x = fmaf(v1.x, rs1, acc1.x);
            acc1.y = fmaf(v1.y, rs1, acc1.y);
            acc1.z = fmaf(v1.z, rs1, acc1.z);
            acc1.w = fmaf(v1.w, rs1, acc1.w);
        }
        if (j < deg) {
            int s0 = bk[j];
            float rs0 = rsqrtf(fmaxf((float)od[s0], 1.f));
            float4 v0 = Xv[(size_t)s0 * 32 + lane];
            acc0.x = fmaf(v0.x, rs0, acc0.x);
            acc0.y = fmaf(v0.y, rs0, acc0.y);
            acc0.z = fmaf(v0.z, rs0, acc0.z);
            acc0.w = fmaf(v0.w, rs0, acc0.w);
        }
        float c = rsqrtf(fmaxf((float)cnt, 1.f)) * scale;
        acc0.x = (acc0.x + acc1.x) * c;
        acc0.y = (acc0.y + acc1.y) * c;
        acc0.z = (acc0.z + acc1.z) * c;
        acc0.w = (acc0.w + acc1.w) * c;
    }
    __nv_bfloat16 h0 = __float2bfloat16(acc0.x);
    __nv_bfloat16 h1 = __float2bfloat16(acc0.y);
    __nv_bfloat16 h2 = __float2bfloat16(acc0.z);
    __nv_bfloat16 h3 = __float2bfloat16(acc0.w);
    __nv_bfloat16 l0 = __float2bfloat16(acc0.x - __bfloat162float(h0));
    __nv_bfloat16 l1 = __float2bfloat16(acc0.y - __bfloat162float(h1));
    __nv_bfloat16 l2 = __float2bfloat16(acc0.z - __bfloat162float(h2));
    __nv_bfloat16 l3 = __float2bfloat16(acc0.w - __bfloat162float(h3));

    int r = gw & 127;
    uint32_t p = swz_off(r, lane >> 1) + (uint32_t)((lane & 1) * 8);
    char* bh = (char*)g_Ahi + (size_t)tile * TILE_ELEMS * 2 + p;
    char* bl = (char*)g_Alo + (size_t)tile * TILE_ELEMS * 2 + p;
    union { __nv_bfloat162 b2[2]; uint2 u; } uh, ul;
    uh.b2[0] = __halves2bfloat162(h0, h1); uh.b2[1] = __halves2bfloat162(h2, h3);
    ul.b2[0] = __halves2bfloat162(l0, l1); ul.b2[1] = __halves2bfloat162(l2, l3);
    *(uint2*)bh = uh.u;
    *(uint2*)bl = ul.u;
}

// ---------------------------------------------------------------------------
// HMMA GEMM: 128x128 output per block, 16 warps (8x2, warp tile 16x64).
// cp.async double-buffered A staging; B (L2-resident) copied per chunk.
// 3 split products per relation chunk, fp32 register accumulators.
#define OFF_A0HI 0
#define OFF_A0LO 32768
#define OFF_A1HI 65536
#define OFF_A1LO 98304
#define OFF_BHI  131072
#define OFF_BLO  163840
#define SMEM_BYTES 196608

__device__ __forceinline__ void stage_a_async(uint32_t sb, int buf, int tile, int tid) {
    uint32_t shi = sb + (buf ? OFF_A1HI : OFF_A0HI);
    uint32_t slo = sb + (buf ? OFF_A1LO : OFF_A0LO);
    const char* gh = (const char*)g_Ahi + (size_t)tile * TILE_ELEMS * 2;
    const char* gl = (const char*)g_Alo + (size_t)tile * TILE_ELEMS * 2;
#pragma unroll
    for (int i = 0; i < 4; i++) {
        uint32_t off = (uint32_t)(tid + i * 512) * 16;
        CP_ASYNC16(shi + off, gh + off);
        CP_ASYNC16(slo + off, gl + off);
    }
}

// One K=128 pass: acc += A(sA) @ B(sB)^T.
__device__ __forceinline__ void mma_pass(uint32_t sA, uint32_t sB,
                                         float acc[8][4], int lane,
                                         int wm, int wn) {
#pragma unroll
    for (int ks = 0; ks < 8; ks++) {
        uint32_t a[4];
        {
            int row = wm * 16 + (lane & 15);
            int chunk = ks * 2 + (lane >> 4);
            LDSM_X4(a[0], a[1], a[2], a[3], sA + swz_off(row, chunk));
        }
        uint32_t bfr[8][2];
#pragma unroll
        for (int jp = 0; jp < 4; jp++) {
            int quarter = lane >> 3;
            int nrow = wn * 64 + (jp * 2 + (quarter >> 1)) * 8 + (lane & 7);
            int chunk = ks * 2 + (quarter & 1);
            LDSM_X4(bfr[jp * 2][0], bfr[jp * 2][1], bfr[jp * 2 + 1][0], bfr[jp * 2 + 1][1],
                    sB + swz_off(nrow, chunk));
        }
#pragma unroll
        for (int nt = 0; nt < 8; nt++)
            mma16816(acc[nt], a, bfr[nt]);
    }
}

__global__ void __launch_bounds__(512, 1)
tc_gemm_kernel(const float* __restrict__ b_sc, const float* __restrict__ b_in,
               const float* __restrict__ b_ni, const float* __restrict__ b_ii,
               const float* __restrict__ b_si, const float* __restrict__ b_is,
               float* __restrict__ out) {
    extern __shared__ char smem[];
    uint32_t sb = smem_u32(smem);
    int tid = threadIdx.x, wid = tid >> 5, lane = tid & 31;
    int wm = wid >> 1, wn = wid & 1;
    int b = blockIdx.x;

    // Heavy blocks first: inst (nrel=3), svc (nrel=2), node (nrel=1).
    int nrel, bl, n_rows;
    int tiles[3]; int rels[3];
    const float* bias0; const float* bias1; const float* bias2;
    float scale; float* obase;
    if (b < 391) {
        bl = b; nrel = 3; n_rows = N_INST; scale = 1.f / 3.f;
        obase = out + (size_t)N_NODE * D;
        tiles[0] = 236 + bl; tiles[1] = 627 + bl; tiles[2] = 1018 + bl;
        rels[0] = 2; rels[1] = 3; rels[2] = 4;
        bias0 = b_ni; bias1 = b_ii; bias2 = b_si;
    } else if (b < 548) {
        bl = b - 391; nrel = 2; n_rows = N_SVC; scale = 0.5f;
        obase = out + (size_t)(N_NODE + N_INST) * D;
        tiles[0] = bl; tiles[1] = 1409 + bl;
        rels[0] = 0; rels[1] = 5;
        bias0 = b_sc; bias1 = b_is; bias2 = 0;
    } else {
        bl = b - 548; nrel = 1; n_rows = N_NODE; scale = 1.0f; obase = out;
        tiles[0] = 157 + bl; rels[0] = 1;
        bias0 = b_in; bias1 = 0; bias2 = 0;
    }
    int row0 = bl * 128;

    float acc[8][4];
#pragma unroll
    for (int j = 0; j < 8; j++)
#pragma unroll
        for (int k = 0; k < 4; k++) acc[j][k] = 0.f;

    // Prefetch A(0).
    stage_a_async(sb, 0, tiles[0], tid);
    CP_COMMIT();

    for (int r = 0; r < nrel; r++) {
        if (r + 1 < nrel) {
            stage_a_async(sb, (r + 1) & 1, tiles[r + 1], tid);
            CP_COMMIT();
            CP_WAIT1();            // A(r) complete
        } else {
            CP_WAIT0();
        }
        __syncthreads();           // A(r) visible; prior chunk's compute done

        // Copy B(r) from L2 (shared by all blocks of this dst type).
        {
            const uint4* gbh = (const uint4*)(g_Bhi + (size_t)rels[r] * TILE_ELEMS);
            const uint4* gbl = (const uint4*)(g_Blo + (size_t)rels[r] * TILE_ELEMS);
            uint4* dbh = (uint4*)(smem + OFF_BHI);
            uint4* dbl = (uint4*)(smem + OFF_BLO);
#pragma unroll
            for (int i = 0; i < 4; i++) {
                int idx = tid + i * 512;
                dbh[idx] = gbh[idx];
                dbl[idx] = gbl[idx];
            }
        }
        __syncthreads();

        uint32_t sAhi = sb + ((r & 1) ? OFF_A1HI : OFF_A0HI);
        uint32_t sAlo = sb + ((r & 1) ? OFF_A1LO : OFF_A0LO);
        mma_pass(sAhi, sb + OFF_BHI, acc, lane, wm, wn);  // hi*hi
        mma_pass(sAlo, sb + OFF_BHI, acc, lane, wm, wn);  // lo*hi
        mma_pass(sAhi, sb + OFF_BLO, acc, lane, wm, wn);  // hi*lo
    }

    // Epilogue: combined scaled bias + relu, direct float2 stores.
    float2 bb[8];
#pragma unroll
    for (int nt = 0; nt < 8; nt++) {
        int c = wn * 64 + nt * 8 + (lane & 3) * 2;
        float v0 = bias0[c], v1 = bias0[c + 1];
        if (nrel > 1) { v0 += bias1[c]; v1 += bias1[c + 1]; }
        if (nrel > 2) { v0 += bias2[c]; v1 += bias2[c + 1]; }
        bb[nt].x = v0 * scale;
        bb[nt].y = v1 * scale;
    }
    int rbase = row0 + wm * 16 + (lane >> 2);
#pragma unroll
    for (int half = 0; half < 2; half++) {
        int grow = rbase + half * 8;
        if (grow >= n_rows) continue;
        float* orow = obase + (size_t)grow * D;
#pragma unroll
        for (int nt = 0; nt < 8; nt++) {
            int c = wn * 64 + nt * 8 + (lane & 3) * 2;
            float2 v;
            v.x = fmaxf(acc[nt][half * 2 + 0] + bb[nt].x, 0.f);
            v.y = fmaxf(acc[nt][half * 2 + 1] + bb[nt].y, 0.f);
            *(float2*)(orow + c) = v;
        }
    }
}

// ---------------------------------------------------------------------------
extern "C" void kernel_launch(void* const* d_in, const int* in_sizes, int n_in,
                              void* d_out, int out_size) {
    const float* node_feat = (const float*)d_in[0];
    const float* inst_feat = (const float*)d_in[1];
    const float* svc_feat  = (const float*)d_in[2];

    const int*   e_src[NREL];
    const int*   e_dst[NREL];
    const float* W[NREL];
    const float* B[NREL];
    for (int r = 0; r < NREL; r++) {
        e_src[r] = (const int*)  d_in[3 + r * 4 + 0];
        e_dst[r] = (const int*)  d_in[3 + r * 4 + 1];
        W[r]     = (const float*)d_in[3 + r * 4 + 2];
        B[r]     = (const float*)d_in[3 + r * 4 + 3];
    }

    float* out = (float*)d_out;

    static bool attr_set = false;
    if (!attr_set) {
        cudaFuncSetAttribute(tc_gemm_kernel,
                             cudaFuncAttributeMaxDynamicSharedMemorySize, SMEM_BYTES);
        attr_set = true;
    }

    // 1. zero counts
    zero_counts_kernel<<<512, 256>>>();

    // 2. build buckets + out-degrees
    build_kernel<<<(NREL * NEDGE + 255) / 256, 256>>>(
        e_src[0], e_dst[0], e_src[1], e_dst[1], e_src[2], e_dst[2],
        e_src[3], e_dst[3], e_src[4], e_dst[4], e_src[5], e_dst[5]);

    // 3. gather -> split-bf16 swizzled A tiles (+ 6 W-prep blocks)
    gather_all_kernel<<<GATHER_BLOCKS + NREL, 256>>>(
        svc_feat, inst_feat, node_feat, inst_feat, svc_feat, inst_feat,
        W[0], W[1], W[2], W[3], W[4], W[5]);

    // 4. tensor-core GEMM (627 blocks, heavy-first)
    tc_gemm_kernel<<<627, 512, SMEM_BYTES>>>(
        B[0], B[1], B[2], B[3], B[4], B[5], out);
}

// round 14
// speedup vs baseline: 1.1521x; 1.1521x over previous
#include <cuda_runtime.h>
#include <cuda_bf16.h>
#include <cstddef>
#include <cstdint>

#define N_NODE 10000
#define N_INST 50000
#define N_SVC  20000
#define NEDGE  200000
#define D      128
#define NREL   6
#define MAXN   50000
#define TOTAL_DST_ROWS 200000
#define CAP 128
#define TILE_ELEMS 16384         // 128x128 bf16 elements per tile (32 KB)
#define NTILE 1566               // sc:157 in:79 ni:391 ii:391 si:391 is:157
// Tile bases: sc=0, in=157, ni=236, ii=627, si=1018, is=1409

// Static scratch.
__device__ int   g_bucket[(size_t)TOTAL_DST_ROWS * CAP];   // ~102 MB
__device__ int   g_cnt[TOTAL_DST_ROWS];
__device__ int   g_outdeg[NREL * MAXN];
__device__ __nv_bfloat16 g_Ahi[(size_t)NTILE * TILE_ELEMS]; // 51.3 MB
__device__ __nv_bfloat16 g_Alo[(size_t)NTILE * TILE_ELEMS]; // 51.3 MB
__device__ __nv_bfloat16 g_Bhi[NREL * TILE_ELEMS];
__device__ __nv_bfloat16 g_Blo[NREL * TILE_ELEMS];

// ---------------------------------------------------------------------------
__device__ __forceinline__ uint32_t smem_u32(const void* p) {
    uint32_t a;
    asm("{ .reg .u64 t; cvta.to.shared.u64 t, %1; cvt.u32.u64 %0, t; }"
        : "=r"(a) : "l"(p));
    return a;
}

// ldmatrix XOR swizzle: 256 B/row; 16B chunk id XORed with (row&7) in low 3 bits.
__device__ __forceinline__ uint32_t swz_off(int r, int chunk) {
    return (uint32_t)(r * 256 + (((chunk & 8) | ((chunk ^ (r & 7)) & 7)) << 4));
}

#define LDSM_X4(r0, r1, r2, r3, addr) \
    asm volatile("ldmatrix.sync.aligned.m8n8.x4.shared.b16 {%0,%1,%2,%3}, [%4];" \
                 : "=r"(r0), "=r"(r1), "=r"(r2), "=r"(r3) : "r"(addr))

__device__ __forceinline__ void mma16816(float* c, const uint32_t* a, const uint32_t* b) {
    asm volatile("mma.sync.aligned.m16n8k16.row.col.f32.bf16.bf16.f32 "
                 "{%0,%1,%2,%3}, {%4,%5,%6,%7}, {%8,%9}, {%0,%1,%2,%3};"
                 : "+f"(c[0]), "+f"(c[1]), "+f"(c[2]), "+f"(c[3])
                 : "r"(a[0]), "r"(a[1]), "r"(a[2]), "r"(a[3]),
                   "r"(b[0]), "r"(b[1]));
}

#define CP_ASYNC16(sm, g) \
    asm volatile("cp.async.cg.shared.global [%0], [%1], 16;" :: "r"(sm), "l"(g))
#define CP_COMMIT() asm volatile("cp.async.commit_group;" ::: "memory")
#define CP_WAIT0()  asm volatile("cp.async.wait_group 0;" ::: "memory")
#define CP_WAIT1()  asm volatile("cp.async.wait_group 1;" ::: "memory")

// ---------------------------------------------------------------------------
__global__ void zero_counts_kernel() {
    int i = blockIdx.x * blockDim.x + threadIdx.x;
    int stride = gridDim.x * blockDim.x;
    for (int j = i; j < TOTAL_DST_ROWS; j += stride) g_cnt[j] = 0;
    for (int j = i; j < NREL * MAXN; j += stride) g_outdeg[j] = 0;
}

// ---------------------------------------------------------------------------
__global__ void build_kernel(const int* __restrict__ s0, const int* __restrict__ d0,
                             const int* __restrict__ s1, const int* __restrict__ d1,
                             const int* __restrict__ s2, const int* __restrict__ d2,
                             const int* __restrict__ s3, const int* __restrict__ d3,
                             const int* __restrict__ s4, const int* __restrict__ d4,
                             const int* __restrict__ s5, const int* __restrict__ d5) {
    int i = blockIdx.x * blockDim.x + threadIdx.x;
    if (i >= NREL * NEDGE) return;
    int rel = i / NEDGE;
    int e = i - rel * NEDGE;
    const int* sp; const int* dp; int off;
    switch (rel) {
        case 0: sp = s0; dp = d0; off = 0;      break;
        case 1: sp = s1; dp = d1; off = 20000;  break;
        case 2: sp = s2; dp = d2; off = 30000;  break;
        case 3: sp = s3; dp = d3; off = 80000;  break;
        case 4: sp = s4; dp = d4; off = 130000; break;
        default: sp = s5; dp = d5; off = 180000; break;
    }
    int s = sp[e];
    int d = dp[e];
    atomicAdd(&g_outdeg[rel * MAXN + s], 1);
    int pos = atomicAdd(&g_cnt[off + d], 1);
    if (pos < CAP) g_bucket[(size_t)(off + d) * CAP + pos] = s;
}

// ---------------------------------------------------------------------------
// Pre-split W into K-major (B[n][k]) swizzled bf16 tiles.
__global__ void prep_w_kernel(const float* __restrict__ W0, const float* __restrict__ W1,
                              const float* __restrict__ W2, const float* __restrict__ W3,
                              const float* __restrict__ W4, const float* __restrict__ W5) {
    int rel = blockIdx.x;
    const float* W;
    switch (rel) {
        case 0: W = W0; break; case 1: W = W1; break; case 2: W = W2; break;
        case 3: W = W3; break; case 4: W = W4; break; default: W = W5; break;
    }
    char* bh = (char*)(g_Bhi + (size_t)rel * TILE_ELEMS);
    char* bl = (char*)(g_Blo + (size_t)rel * TILE_ELEMS);
    for (int idx = threadIdx.x; idx < D * D; idx += blockDim.x) {
        int k = idx >> 7, n = idx & 127;       // W[k][n] -> B[n][k]
        float v = W[idx];
        __nv_bfloat16 h = __float2bfloat16(v);
        __nv_bfloat16 l = __float2bfloat16(v - __bfloat162float(h));
        uint32_t p = swz_off(n, k >> 3) + (uint32_t)((k & 7) * 2);
        *(__nv_bfloat16*)(bh + p) = h;
        *(__nv_bfloat16*)(bl + p) = l;
    }
}

// ---------------------------------------------------------------------------
// Gather: warp per padded dst row; writes split-bf16 into swizzled tiles.
// (Exact round-11 form — measured 81.4us.)
__global__ void gather_all_kernel(const float* __restrict__ X0,  // svc  (sc)
                                  const float* __restrict__ X1,  // inst (in)
                                  const float* __restrict__ X2,  // node (ni)
                                  const float* __restrict__ X3,  // inst (ii)
                                  const float* __restrict__ X4,  // svc  (si)
                                  const float* __restrict__ X5)  // inst (is)
{
    int gw = (blockIdx.x * blockDim.x + threadIdx.x) >> 5;   // padded row id
    int lane = threadIdx.x & 31;
    int tile = gw >> 7;
    if (tile >= NTILE) return;

    int rel, pbase, segN, tbase; const float* X; float scale;
    if      (tile < 157)  { rel = 0; X = X0; scale = 0.5f;      pbase = 0;      segN = 20000; tbase = 0; }
    else if (tile < 236)  { rel = 1; X = X1; scale = 1.0f;      pbase = 20000;  segN = 10000; tbase = 157; }
    else if (tile < 627)  { rel = 2; X = X2; scale = 1.f / 3.f; pbase = 30000;  segN = 50000; tbase = 236; }
    else if (tile < 1018) { rel = 3; X = X3; scale = 1.f / 3.f; pbase = 80000;  segN = 50000; tbase = 627; }
    else if (tile < 1409) { rel = 4; X = X4; scale = 1.f / 3.f; pbase = 130000; segN = 50000; tbase = 1018; }
    else                  { rel = 5; X = X5; scale = 0.5f;      pbase = 180000; segN = 20000; tbase = 1409; }

    int local = gw - (tbase << 7);
    float4 acc = make_float4(0.f, 0.f, 0.f, 0.f);
    if (local < segN) {
        int g = pbase + local;
        int cnt = g_cnt[g];
        int deg = cnt < CAP ? cnt : CAP;
        const int* bk = g_bucket + (size_t)g * CAP;
        const int* od = g_outdeg + rel * MAXN;
        const float4* Xv = (const float4*)X;
        for (int j = 0; j < deg; j++) {
            int s = bk[j];
            float rs = rsqrtf(fmaxf((float)od[s], 1.f));
            float4 v = Xv[(size_t)s * 32 + lane];
            acc.x = fmaf(v.x, rs, acc.x);
            acc.y = fmaf(v.y, rs, acc.y);
            acc.z = fmaf(v.z, rs, acc.z);
            acc.w = fmaf(v.w, rs, acc.w);
        }
        float c = rsqrtf(fmaxf((float)cnt, 1.f)) * scale;
        acc.x *= c; acc.y *= c; acc.z *= c; acc.w *= c;
    }
    __nv_bfloat16 h0 = __float2bfloat16(acc.x);
    __nv_bfloat16 h1 = __float2bfloat16(acc.y);
    __nv_bfloat16 h2 = __float2bfloat16(acc.z);
    __nv_bfloat16 h3 = __float2bfloat16(acc.w);
    __nv_bfloat16 l0 = __float2bfloat16(acc.x - __bfloat162float(h0));
    __nv_bfloat16 l1 = __float2bfloat16(acc.y - __bfloat162float(h1));
    __nv_bfloat16 l2 = __float2bfloat16(acc.z - __bfloat162float(h2));
    __nv_bfloat16 l3 = __float2bfloat16(acc.w - __bfloat162float(h3));

    int r = gw & 127;
    uint32_t p = swz_off(r, lane >> 1) + (uint32_t)((lane & 1) * 8);
    char* bh = (char*)g_Ahi + (size_t)tile * TILE_ELEMS * 2 + p;
    char* bl = (char*)g_Alo + (size_t)tile * TILE_ELEMS * 2 + p;
    union { __nv_bfloat162 b2[2]; uint2 u; } uh, ul;
    uh.b2[0] = __halves2bfloat162(h0, h1); uh.b2[1] = __halves2bfloat162(h2, h3);
    ul.b2[0] = __halves2bfloat162(l0, l1); ul.b2[1] = __halves2bfloat162(l2, l3);
    *(uint2*)bh = uh.u;
    *(uint2*)bl = ul.u;
}

// ---------------------------------------------------------------------------
// HMMA GEMM: 128x128 output per block, 8 warps (4x2, warp tile 32x64), 256 thr.
// cp.async double-buffered A staging; B (L2-resident) copied per chunk.
// 3 split products per relation chunk, fp32 register accumulators.
#define OFF_A0HI 0
#define OFF_A0LO 32768
#define OFF_A1HI 65536
#define OFF_A1LO 98304
#define OFF_BHI  131072
#define OFF_BLO  163840
#define SMEM_BYTES 196608

__device__ __forceinline__ void stage_a_async(uint32_t sb, int buf, int tile, int tid) {
    uint32_t shi = sb + (buf ? OFF_A1HI : OFF_A0HI);
    uint32_t slo = sb + (buf ? OFF_A1LO : OFF_A0LO);
    const char* gh = (const char*)g_Ahi + (size_t)tile * TILE_ELEMS * 2;
    const char* gl = (const char*)g_Alo + (size_t)tile * TILE_ELEMS * 2;
#pragma unroll
    for (int i = 0; i < 8; i++) {
        uint32_t off = (uint32_t)(tid + i * 256) * 16;
        CP_ASYNC16(shi + off, gh + off);
        CP_ASYNC16(slo + off, gl + off);
    }
}

// One K=128 pass: acc += A(sA) @ B(sB)^T.  (Round-11 validated mapping.)
__device__ __forceinline__ void mma_pass(uint32_t sA, uint32_t sB,
                                         float acc[2][8][4], int lane,
                                         int wm, int wn) {
#pragma unroll
    for (int ks = 0; ks < 8; ks++) {
        uint32_t a[2][4];
#pragma unroll
        for (int mt = 0; mt < 2; mt++) {
            int row = wm * 32 + mt * 16 + (lane & 15);
            int chunk = ks * 2 + (lane >> 4);
            LDSM_X4(a[mt][0], a[mt][1], a[mt][2], a[mt][3], sA + swz_off(row, chunk));
        }
        uint32_t bfr[8][2];
#pragma unroll
        for (int jp = 0; jp < 4; jp++) {
            int quarter = lane >> 3;
            int nrow = wn * 64 + (jp * 2 + (quarter >> 1)) * 8 + (lane & 7);
            int chunk = ks * 2 + (quarter & 1);
            LDSM_X4(bfr[jp * 2][0], bfr[jp * 2][1], bfr[jp * 2 + 1][0], bfr[jp * 2 + 1][1],
                    sB + swz_off(nrow, chunk));
        }
#pragma unroll
        for (int mt = 0; mt < 2; mt++)
#pragma unroll
            for (int nt = 0; nt < 8; nt++)
                mma16816(acc[mt][nt], a[mt], bfr[nt]);
    }
}

__global__ void __launch_bounds__(256, 1)
tc_gemm_kernel(const float* __restrict__ b_sc, const float* __restrict__ b_in,
               const float* __restrict__ b_ni, const float* __restrict__ b_ii,
               const float* __restrict__ b_si, const float* __restrict__ b_is,
               float* __restrict__ out) {
    extern __shared__ char smem[];
    uint32_t sb = smem_u32(smem);
    int tid = threadIdx.x, wid = tid >> 5, lane = tid & 31;
    int wm = wid >> 1, wn = wid & 1;
    int b = blockIdx.x;

    // Heavy blocks first: inst (nrel=3), svc (nrel=2), node (nrel=1).
    int nrel, bl, n_rows;
    int tiles[3]; int rels[3];
    const float* bias0; const float* bias1; const float* bias2;
    float scale; float* obase;
    if (b < 391) {
        bl = b; nrel = 3; n_rows = N_INST; scale = 1.f / 3.f;
        obase = out + (size_t)N_NODE * D;
        tiles[0] = 236 + bl; tiles[1] = 627 + bl; tiles[2] = 1018 + bl;
        rels[0] = 2; rels[1] = 3; rels[2] = 4;
        bias0 = b_ni; bias1 = b_ii; bias2 = b_si;
    } else if (b < 548) {
        bl = b - 391; nrel = 2; n_rows = N_SVC; scale = 0.5f;
        obase = out + (size_t)(N_NODE + N_INST) * D;
        tiles[0] = bl; tiles[1] = 1409 + bl;
        rels[0] = 0; rels[1] = 5;
        bias0 = b_sc; bias1 = b_is; bias2 = 0;
    } else {
        bl = b - 548; nrel = 1; n_rows = N_NODE; scale = 1.0f; obase = out;
        tiles[0] = 157 + bl; rels[0] = 1;
        bias0 = b_in; bias1 = 0; bias2 = 0;
    }
    int row0 = bl * 128;

    float acc[2][8][4];
#pragma unroll
    for (int i = 0; i < 2; i++)
#pragma unroll
        for (int j = 0; j < 8; j++)
#pragma unroll
            for (int k = 0; k < 4; k++) acc[i][j][k] = 0.f;

    // Prefetch A(0).
    stage_a_async(sb, 0, tiles[0], tid);
    CP_COMMIT();

    for (int r = 0; r < nrel; r++) {
        if (r + 1 < nrel) {
            stage_a_async(sb, (r + 1) & 1, tiles[r + 1], tid);
            CP_COMMIT();
            CP_WAIT1();            // A(r) complete
        } else {
            CP_WAIT0();
        }
        __syncthreads();           // A(r) visible; prior chunk's compute done

        // Copy B(r) from L2 (shared by all blocks of this dst type).
        {
            const uint4* gbh = (const uint4*)(g_Bhi + (size_t)rels[r] * TILE_ELEMS);
            const uint4* gbl = (const uint4*)(g_Blo + (size_t)rels[r] * TILE_ELEMS);
            uint4* dbh = (uint4*)(smem + OFF_BHI);
            uint4* dbl = (uint4*)(smem + OFF_BLO);
#pragma unroll
            for (int i = 0; i < 8; i++) {
                int idx = tid + i * 256;
                dbh[idx] = gbh[idx];
                dbl[idx] = gbl[idx];
            }
        }
        __syncthreads();

        uint32_t sAhi = sb + ((r & 1) ? OFF_A1HI : OFF_A0HI);
        uint32_t sAlo = sb + ((r & 1) ? OFF_A1LO : OFF_A0LO);
        mma_pass(sAhi, sb + OFF_BHI, acc, lane, wm, wn);  // hi*hi
        mma_pass(sAlo, sb + OFF_BHI, acc, lane, wm, wn);  // lo*hi
        mma_pass(sAhi, sb + OFF_BLO, acc, lane, wm, wn);  // hi*lo
    }

    // Epilogue: combined scaled bias + relu, direct float2 stores.
    float2 bb[8];
#pragma unroll
    for (int nt = 0; nt < 8; nt++) {
        int c = wn * 64 + nt * 8 + (lane & 3) * 2;
        float v0 = bias0[c], v1 = bias0[c + 1];
        if (nrel > 1) { v0 += bias1[c]; v1 += bias1[c + 1]; }
        if (nrel > 2) { v0 += bias2[c]; v1 += bias2[c + 1]; }
        bb[nt].x = v0 * scale;
        bb[nt].y = v1 * scale;
    }
#pragma unroll
    for (int mt = 0; mt < 2; mt++) {
        int rbase = row0 + wm * 32 + mt * 16 + (lane >> 2);
#pragma unroll
        for (int half = 0; half < 2; half++) {
            int grow = rbase + half * 8;
            if (grow >= n_rows) continue;
            float* orow = obase + (size_t)grow * D;
#pragma unroll
            for (int nt = 0; nt < 8; nt++) {
                int c = wn * 64 + nt * 8 + (lane & 3) * 2;
                float2 v;
                v.x = fmaxf(acc[mt][nt][half * 2 + 0] + bb[nt].x, 0.f);
                v.y = fmaxf(acc[mt][nt][half * 2 + 1] + bb[nt].y, 0.f);
                *(float2*)(orow + c) = v;
            }
        }
    }
}

// ---------------------------------------------------------------------------
extern "C" void kernel_launch(void* const* d_in, const int* in_sizes, int n_in,
                              void* d_out, int out_size) {
    const float* node_feat = (const float*)d_in[0];
    const float* inst_feat = (const float*)d_in[1];
    const float* svc_feat  = (const float*)d_in[2];

    const int*   e_src[NREL];
    const int*   e_dst[NREL];
    const float* W[NREL];
    const float* B[NREL];
    for (int r = 0; r < NREL; r++) {
        e_src[r] = (const int*)  d_in[3 + r * 4 + 0];
        e_dst[r] = (const int*)  d_in[3 + r * 4 + 1];
        W[r]     = (const float*)d_in[3 + r * 4 + 2];
        B[r]     = (const float*)d_in[3 + r * 4 + 3];
    }

    float* out = (float*)d_out;

    static bool attr_set = false;
    if (!attr_set) {
        cudaFuncSetAttribute(tc_gemm_kernel,
                             cudaFuncAttributeMaxDynamicSharedMemorySize, SMEM_BYTES);
        attr_set = true;
    }

    // 1. zero counts
    zero_counts_kernel<<<512, 256>>>();

    // 2. build buckets + out-degrees
    build_kernel<<<(NREL * NEDGE + 255) / 256, 256>>>(
        e_src[0], e_dst[0], e_src[1], e_dst[1], e_src[2], e_dst[2],
        e_src[3], e_dst[3], e_src[4], e_dst[4], e_src[5], e_dst[5]);

    // 3. pre-split W tiles
    prep_w_kernel<<<NREL, 256>>>(W[0], W[1], W[2], W[3], W[4], W[5]);

    // 4. gather -> split-bf16 swizzled A tiles (round-11 form)
    gather_all_kernel<<<NTILE * 16, 256>>>(
        svc_feat, inst_feat, node_feat, inst_feat, svc_feat, inst_feat);

    // 5. tensor-core GEMM (627 blocks, heavy-first, pipelined A)
    tc_gemm_kernel<<<627, 256, SMEM_BYTES>>>(
        B[0], B[1], B[2], B[3], B[4], B[5], out);
}

// round 16
// speedup vs baseline: 1.1862x; 1.0295x over previous
#include <cuda_runtime.h>
#include <cuda_bf16.h>
#include <cstddef>
#include <cstdint>

#define N_NODE 10000
#define N_INST 50000
#define N_SVC  20000
#define NEDGE  200000
#define D      128
#define NREL   6
#define MAXN   50000
#define TOTAL_DST_ROWS 200000
#define CAP 128
#define TILE_ELEMS 16384         // 128x128 bf16 elements per tile (32 KB)
#define NTILE 1566               // sc:157 in:79 ni:391 ii:391 si:391 is:157
// Tile bases: sc=0, in=157, ni=236, ii=627, si=1018, is=1409

// Static scratch.
__device__ int   g_bucket[(size_t)TOTAL_DST_ROWS * CAP];   // ~102 MB
__device__ int   g_cnt[TOTAL_DST_ROWS];
__device__ int   g_outdeg[NREL * MAXN];
__device__ float g_rsq[NREL * MAXN];                       // rsqrt(max(outdeg,1))
__device__ __nv_bfloat16 g_Ahi[(size_t)NTILE * TILE_ELEMS]; // 51.3 MB
__device__ __nv_bfloat16 g_Alo[(size_t)NTILE * TILE_ELEMS]; // 51.3 MB
__device__ __nv_bfloat16 g_Bhi[NREL * TILE_ELEMS];
__device__ __nv_bfloat16 g_Blo[NREL * TILE_ELEMS];

// ---------------------------------------------------------------------------
__device__ __forceinline__ uint32_t smem_u32(const void* p) {
    uint32_t a;
    asm("{ .reg .u64 t; cvta.to.shared.u64 t, %1; cvt.u32.u64 %0, t; }"
        : "=r"(a) : "l"(p));
    return a;
}

// ldmatrix XOR swizzle: 256 B/row; 16B chunk id XORed with (row&7) in low 3 bits.
__device__ __forceinline__ uint32_t swz_off(int r, int chunk) {
    return (uint32_t)(r * 256 + (((chunk & 8) | ((chunk ^ (r & 7)) & 7)) << 4));
}

#define LDSM_X4(r0, r1, r2, r3, addr) \
    asm volatile("ldmatrix.sync.aligned.m8n8.x4.shared.b16 {%0,%1,%2,%3}, [%4];" \
                 : "=r"(r0), "=r"(r1), "=r"(r2), "=r"(r3) : "r"(addr))

__device__ __forceinline__ void mma16816(float* c, const uint32_t* a, const uint32_t* b) {
    asm volatile("mma.sync.aligned.m16n8k16.row.col.f32.bf16.bf16.f32 "
                 "{%0,%1,%2,%3}, {%4,%5,%6,%7}, {%8,%9}, {%0,%1,%2,%3};"
                 : "+f"(c[0]), "+f"(c[1]), "+f"(c[2]), "+f"(c[3])
                 : "r"(a[0]), "r"(a[1]), "r"(a[2]), "r"(a[3]),
                   "r"(b[0]), "r"(b[1]));
}

#define CP_ASYNC16(sm, g) \
    asm volatile("cp.async.cg.shared.global [%0], [%1], 16;" :: "r"(sm), "l"(g))
#define CP_COMMIT() asm volatile("cp.async.commit_group;" ::: "memory")
#define CP_WAIT0()  asm volatile("cp.async.wait_group 0;" ::: "memory")

// ---------------------------------------------------------------------------
__global__ void zero_counts_kernel() {
    int i = blockIdx.x * blockDim.x + threadIdx.x;
    int stride = gridDim.x * blockDim.x;
    for (int j = i; j < TOTAL_DST_ROWS; j += stride) g_cnt[j] = 0;
    for (int j = i; j < NREL * MAXN; j += stride) g_outdeg[j] = 0;
}

// ---------------------------------------------------------------------------
__global__ void build_kernel(const int* __restrict__ s0, const int* __restrict__ d0,
                             const int* __restrict__ s1, const int* __restrict__ d1,
                             const int* __restrict__ s2, const int* __restrict__ d2,
                             const int* __restrict__ s3, const int* __restrict__ d3,
                             const int* __restrict__ s4, const int* __restrict__ d4,
                             const int* __restrict__ s5, const int* __restrict__ d5) {
    int i = blockIdx.x * blockDim.x + threadIdx.x;
    if (i >= NREL * NEDGE) return;
    int rel = i / NEDGE;
    int e = i - rel * NEDGE;
    const int* sp; const int* dp; int off;
    switch (rel) {
        case 0: sp = s0; dp = d0; off = 0;      break;
        case 1: sp = s1; dp = d1; off = 20000;  break;
        case 2: sp = s2; dp = d2; off = 30000;  break;
        case 3: sp = s3; dp = d3; off = 80000;  break;
        case 4: sp = s4; dp = d4; off = 130000; break;
        default: sp = s5; dp = d5; off = 180000; break;
    }
    int s = sp[e];
    int d = dp[e];
    atomicAdd(&g_outdeg[rel * MAXN + s], 1);
    int pos = atomicAdd(&g_cnt[off + d], 1);
    if (pos < CAP) g_bucket[(size_t)(off + d) * CAP + pos] = s;
}

// ---------------------------------------------------------------------------
// Precompute rsqrt(max(outdeg,1)) once — removes 39M in-loop MUFUs from gather.
__global__ void rsq_kernel() {
    int i = blockIdx.x * blockDim.x + threadIdx.x;
    if (i < NREL * MAXN)
        g_rsq[i] = rsqrtf(fmaxf((float)g_outdeg[i], 1.f));
}

// ---------------------------------------------------------------------------
// Pre-split W into K-major (B[n][k]) swizzled bf16 tiles.
__global__ void prep_w_kernel(const float* __restrict__ W0, const float* __restrict__ W1,
                              const float* __restrict__ W2, const float* __restrict__ W3,
                              const float* __restrict__ W4, const float* __restrict__ W5) {
    int rel = blockIdx.x;
    const float* W;
    switch (rel) {
        case 0: W = W0; break; case 1: W = W1; break; case 2: W = W2; break;
        case 3: W = W3; break; case 4: W = W4; break; default: W = W5; break;
    }
    char* bh = (char*)(g_Bhi + (size_t)rel * TILE_ELEMS);
    char* bl = (char*)(g_Blo + (size_t)rel * TILE_ELEMS);
    for (int idx = threadIdx.x; idx < D * D; idx += blockDim.x) {
        int k = idx >> 7, n = idx & 127;       // W[k][n] -> B[n][k]
        float v = W[idx];
        __nv_bfloat16 h = __float2bfloat16(v);
        __nv_bfloat16 l = __float2bfloat16(v - __bfloat162float(h));
        uint32_t p = swz_off(n, k >> 3) + (uint32_t)((k & 7) * 2);
        *(__nv_bfloat16*)(bh + p) = h;
        *(__nv_bfloat16*)(bl + p) = l;
    }
}

// ---------------------------------------------------------------------------
// Gather: warp per padded dst row; writes split-bf16 into swizzled tiles.
// Inner loop: ld src idx -> ld precomputed rsq -> ld.128 X -> 4 FMA.
__global__ void gather_all_kernel(const float* __restrict__ X0,  // svc  (sc)
                                  const float* __restrict__ X1,  // inst (in)
                                  const float* __restrict__ X2,  // node (ni)
                                  const float* __restrict__ X3,  // inst (ii)
                                  const float* __restrict__ X4,  // svc  (si)
                                  const float* __restrict__ X5)  // inst (is)
{
    int gw = (blockIdx.x * blockDim.x + threadIdx.x) >> 5;   // padded row id
    int lane = threadIdx.x & 31;
    int tile = gw >> 7;
    if (tile >= NTILE) return;

    int rel, pbase, segN, tbase; const float* X; float scale;
    if      (tile < 157)  { rel = 0; X = X0; scale = 0.5f;      pbase = 0;      segN = 20000; tbase = 0; }
    else if (tile < 236)  { rel = 1; X = X1; scale = 1.0f;      pbase = 20000;  segN = 10000; tbase = 157; }
    else if (tile < 627)  { rel = 2; X = X2; scale = 1.f / 3.f; pbase = 30000;  segN = 50000; tbase = 236; }
    else if (tile < 1018) { rel = 3; X = X3; scale = 1.f / 3.f; pbase = 80000;  segN = 50000; tbase = 627; }
    else if (tile < 1409) { rel = 4; X = X4; scale = 1.f / 3.f; pbase = 130000; segN = 50000; tbase = 1018; }
    else                  { rel = 5; X = X5; scale = 0.5f;      pbase = 180000; segN = 20000; tbase = 1409; }

    int local = gw - (tbase << 7);
    float4 acc = make_float4(0.f, 0.f, 0.f, 0.f);
    int cnt = 0;
    if (local < segN) {
        int g = pbase + local;
        cnt = g_cnt[g];
        int deg = cnt < CAP ? cnt : CAP;
        const int* bk = g_bucket + (size_t)g * CAP;
        const float* rq = g_rsq + rel * MAXN;
        const float4* Xv = (const float4*)X + lane;
        for (int j = 0; j < deg; j++) {
            int s = bk[j];
            float rs = __ldg(rq + s);
            float4 v = Xv[(size_t)s * 32];
            acc.x = fmaf(v.x, rs, acc.x);
            acc.y = fmaf(v.y, rs, acc.y);
            acc.z = fmaf(v.z, rs, acc.z);
            acc.w = fmaf(v.w, rs, acc.w);
        }
        float c = rsqrtf(fmaxf((float)cnt, 1.f)) * scale;
        acc.x *= c; acc.y *= c; acc.z *= c; acc.w *= c;
    }
    __nv_bfloat16 h0 = __float2bfloat16(acc.x);
    __nv_bfloat16 h1 = __float2bfloat16(acc.y);
    __nv_bfloat16 h2 = __float2bfloat16(acc.z);
    __nv_bfloat16 h3 = __float2bfloat16(acc.w);
    __nv_bfloat16 l0 = __float2bfloat16(acc.x - __bfloat162float(h0));
    __nv_bfloat16 l1 = __float2bfloat16(acc.y - __bfloat162float(h1));
    __nv_bfloat16 l2 = __float2bfloat16(acc.z - __bfloat162float(h2));
    __nv_bfloat16 l3 = __float2bfloat16(acc.w - __bfloat162float(h3));

    int r = gw & 127;
    uint32_t p = swz_off(r, lane >> 1) + (uint32_t)((lane & 1) * 8);
    char* bh = (char*)g_Ahi + (size_t)tile * TILE_ELEMS * 2 + p;
    char* bl = (char*)g_Alo + (size_t)tile * TILE_ELEMS * 2 + p;
    union { __nv_bfloat162 b2[2]; uint2 u; } uh, ul;
    uh.b2[0] = __halves2bfloat162(h0, h1); uh.b2[1] = __halves2bfloat162(h2, h3);
    ul.b2[0] = __halves2bfloat162(l0, l1); ul.b2[1] = __halves2bfloat162(l2, l3);
    *(uint2*)bh = uh.u;
    *(uint2*)bl = ul.u;
}

// ---------------------------------------------------------------------------
// HMMA GEMM: 128x128 output per block, 8 warps (4x2, warp tile 32x64), 256 thr.
// cp.async double-buffered A staging (race-free: staged only after the sync
// proving all warps finished the previous chunk); B copied per chunk.
// 3 split products per relation chunk, fp32 register accumulators.
#define OFF_A0HI 0
#define OFF_A0LO 32768
#define OFF_A1HI 65536
#define OFF_A1LO 98304
#define OFF_BHI  131072
#define OFF_BLO  163840
#define SMEM_BYTES 196608

__device__ __forceinline__ void stage_a_async(uint32_t sb, int buf, int tile, int tid) {
    uint32_t shi = sb + (buf ? OFF_A1HI : OFF_A0HI);
    uint32_t slo = sb + (buf ? OFF_A1LO : OFF_A0LO);
    const char* gh = (const char*)g_Ahi + (size_t)tile * TILE_ELEMS * 2;
    const char* gl = (const char*)g_Alo + (size_t)tile * TILE_ELEMS * 2;
#pragma unroll
    for (int i = 0; i < 8; i++) {
        uint32_t off = (uint32_t)(tid + i * 256) * 16;
        CP_ASYNC16(shi + off, gh + off);
        CP_ASYNC16(slo + off, gl + off);
    }
}

// One K=128 pass: acc += A(sA) @ B(sB)^T.  (Validated mapping.)
__device__ __forceinline__ void mma_pass(uint32_t sA, uint32_t sB,
                                         float acc[2][8][4], int lane,
                                         int wm, int wn) {
#pragma unroll
    for (int ks = 0; ks < 8; ks++) {
        uint32_t a[2][4];
#pragma unroll
        for (int mt = 0; mt < 2; mt++) {
            int row = wm * 32 + mt * 16 + (lane & 15);
            int chunk = ks * 2 + (lane >> 4);
            LDSM_X4(a[mt][0], a[mt][1], a[mt][2], a[mt][3], sA + swz_off(row, chunk));
        }
        uint32_t bfr[8][2];
#pragma unroll
        for (int jp = 0; jp < 4; jp++) {
            int quarter = lane >> 3;
            int nrow = wn * 64 + (jp * 2 + (quarter >> 1)) * 8 + (lane & 7);
            int chunk = ks * 2 + (quarter & 1);
            LDSM_X4(bfr[jp * 2][0], bfr[jp * 2][1], bfr[jp * 2 + 1][0], bfr[jp * 2 + 1][1],
                    sB + swz_off(nrow, chunk));
        }
#pragma unroll
        for (int mt = 0; mt < 2; mt++)
#pragma unroll
            for (int nt = 0; nt < 8; nt++)
                mma16816(acc[mt][nt], a[mt], bfr[nt]);
    }
}

__global__ void __launch_bounds__(256, 1)
tc_gemm_kernel(const float* __restrict__ b_sc, const float* __restrict__ b_in,
               const float* __restrict__ b_ni, const float* __restrict__ b_ii,
               const float* __restrict__ b_si, const float* __restrict__ b_is,
               float* __restrict__ out) {
    extern __shared__ char smem[];
    uint32_t sb = smem_u32(smem);
    int tid = threadIdx.x, wid = tid >> 5, lane = tid & 31;
    int wm = wid >> 1, wn = wid & 1;
    int b = blockIdx.x;

    // Heavy blocks first: inst (nrel=3), svc (nrel=2), node (nrel=1).
    int nrel, bl, n_rows;
    int tiles[3]; int rels[3];
    const float* bias0; const float* bias1; const float* bias2;
    float scale; float* obase;
    if (b < 391) {
        bl = b; nrel = 3; n_rows = N_INST; scale = 1.f / 3.f;
        obase = out + (size_t)N_NODE * D;
        tiles[0] = 236 + bl; tiles[1] = 627 + bl; tiles[2] = 1018 + bl;
        rels[0] = 2; rels[1] = 3; rels[2] = 4;
        bias0 = b_ni; bias1 = b_ii; bias2 = b_si;
    } else if (b < 548) {
        bl = b - 391; nrel = 2; n_rows = N_SVC; scale = 0.5f;
        obase = out + (size_t)(N_NODE + N_INST) * D;
        tiles[0] = bl; tiles[1] = 1409 + bl;
        rels[0] = 0; rels[1] = 5;
        bias0 = b_sc; bias1 = b_is; bias2 = 0;
    } else {
        bl = b - 548; nrel = 1; n_rows = N_NODE; scale = 1.0f; obase = out;
        tiles[0] = 157 + bl; rels[0] = 1;
        bias0 = b_in; bias1 = 0; bias2 = 0;
    }
    int row0 = bl * 128;

    float acc[2][8][4];
#pragma unroll
    for (int i = 0; i < 2; i++)
#pragma unroll
        for (int j = 0; j < 8; j++)
#pragma unroll
            for (int k = 0; k < 4; k++) acc[i][j][k] = 0.f;

    // Prefetch A(0).
    stage_a_async(sb, 0, tiles[0], tid);
    CP_COMMIT();

    for (int r = 0; r < nrel; r++) {
        CP_WAIT0();                // A(r) landed (only one group in flight)
        __syncthreads();           // all warps done with previous chunk's compute

        // Now safe to prefetch A(r+1) into the buffer last read at chunk r-1.
        if (r + 1 < nrel) {
            stage_a_async(sb, (r + 1) & 1, tiles[r + 1], tid);
            CP_COMMIT();
        }

        // Copy B(r) from L2 (shared by all blocks of this dst type).
        {
            const uint4* gbh = (const uint4*)(g_Bhi + (size_t)rels[r] * TILE_ELEMS);
            const uint4* gbl = (const uint4*)(g_Blo + (size_t)rels[r] * TILE_ELEMS);
            uint4* dbh = (uint4*)(smem + OFF_BHI);
            uint4* dbl = (uint4*)(smem + OFF_BLO);
#pragma unroll
            for (int i = 0; i < 8; i++) {
                int idx = tid + i * 256;
                dbh[idx] = gbh[idx];
                dbl[idx] = gbl[idx];
            }
        }
        __syncthreads();

        uint32_t sAhi = sb + ((r & 1) ? OFF_A1HI : OFF_A0HI);
        uint32_t sAlo = sb + ((r & 1) ? OFF_A1LO : OFF_A0LO);
        mma_pass(sAhi, sb + OFF_BHI, acc, lane, wm, wn);  // hi*hi
        mma_pass(sAlo, sb + OFF_BHI, acc, lane, wm, wn);  // lo*hi
        mma_pass(sAhi, sb + OFF_BLO, acc, lane, wm, wn);  // hi*lo
    }

    // Epilogue: combined scaled bias + relu, direct float2 stores.
    float2 bb[8];
#pragma unroll
    for (int nt = 0; nt < 8; nt++) {
        int c = wn * 64 + nt * 8 + (lane & 3) * 2;
        float v0 = bias0[c], v1 = bias0[c + 1];
        if (nrel > 1) { v0 += bias1[c]; v1 += bias1[c + 1]; }
        if (nrel > 2) { v0 += bias2[c]; v1 += bias2[c + 1]; }
        bb[nt].x = v0 * scale;
        bb[nt].y = v1 * scale;
    }
#pragma unroll
    for (int mt = 0; mt < 2; mt++) {
        int rbase = row0 + wm * 32 + mt * 16 + (lane >> 2);
#pragma unroll
        for (int half = 0; half < 2; half++) {
            int grow = rbase + half * 8;
            if (grow >= n_rows) continue;
            float* orow = obase + (size_t)grow * D;
#pragma unroll
            for (int nt = 0; nt < 8; nt++) {
                int c = wn * 64 + nt * 8 + (lane & 3) * 2;
                float2 v;
                v.x = fmaxf(acc[mt][nt][half * 2 + 0] + bb[nt].x, 0.f);
                v.y = fmaxf(acc[mt][nt][half * 2 + 1] + bb[nt].y, 0.f);
                *(float2*)(orow + c) = v;
            }
        }
    }
}

// ---------------------------------------------------------------------------
extern "C" void kernel_launch(void* const* d_in, const int* in_sizes, int n_in,
                              void* d_out, int out_size) {
    const float* node_feat = (const float*)d_in[0];
    const float* inst_feat = (const float*)d_in[1];
    const float* svc_feat  = (const float*)d_in[2];

    const int*   e_src[NREL];
    const int*   e_dst[NREL];
    const float* W[NREL];
    const float* B[NREL];
    for (int r = 0; r < NREL; r++) {
        e_src[r] = (const int*)  d_in[3 + r * 4 + 0];
        e_dst[r] = (const int*)  d_in[3 + r * 4 + 1];
        W[r]     = (const float*)d_in[3 + r * 4 + 2];
        B[r]     = (const float*)d_in[3 + r * 4 + 3];
    }

    float* out = (float*)d_out;

    static bool attr_set = false;
    if (!attr_set) {
        cudaFuncSetAttribute(tc_gemm_kernel,
                             cudaFuncAttributeMaxDynamicSharedMemorySize, SMEM_BYTES);
        attr_set = true;
    }

    // 1. zero counts
    zero_counts_kernel<<<512, 256>>>();

    // 2. build buckets + out-degrees
    build_kernel<<<(NREL * NEDGE + 255) / 256, 256>>>(
        e_src[0], e_dst[0], e_src[1], e_dst[1], e_src[2], e_dst[2],
        e_src[3], e_dst[3], e_src[4], e_dst[4], e_src[5], e_dst[5]);

    // 3. precompute rsqrt(outdeg) + pre-split W tiles (independent)
    rsq_kernel<<<(NREL * MAXN + 255) / 256, 256>>>();
    prep_w_kernel<<<NREL, 256>>>(W[0], W[1], W[2], W[3], W[4], W[5]);

    // 4. gather -> split-bf16 swizzled A tiles
    gather_all_kernel<<<NTILE * 16, 256>>>(
        svc_feat, inst_feat, node_feat, inst_feat, svc_feat, inst_feat);

    // 5. tensor-core GEMM (627 blocks, heavy-first, pipelined A)
    tc_gemm_kernel<<<627, 256, SMEM_BYTES>>>(
        B[0], B[1], B[2], B[3], B[4], B[5], out);
}

// round 17
// speedup vs baseline: 1.3761x; 1.1601x over previous
#include <cuda_runtime.h>
#include <cuda_bf16.h>
#include <cstddef>
#include <cstdint>

#define N_NODE 10000
#define N_INST 50000
#define N_SVC  20000
#define NEDGE  200000
#define D      128
#define NREL   6
#define MAXN   50000
#define TOTAL_DST_ROWS 200000
#define CAP 128
#define TILE_ELEMS 16384         // 128x128 bf16 elements per tile (32 KB)
#define NTILE 1566               // sc:157 in:79 ni:391 ii:391 si:391 is:157
// Tile bases: sc=0, in=157, ni=236, ii=627, si=1018, is=1409

// Static scratch.
__device__ int   g_bucket[(size_t)TOTAL_DST_ROWS * CAP];   // ~102 MB
__device__ int   g_cnt[TOTAL_DST_ROWS];
__device__ int   g_outdeg[NREL * MAXN];
__device__ float g_rsq[NREL * MAXN];                       // rsqrt(max(outdeg,1))
__device__ __nv_bfloat16 g_Ahi[(size_t)NTILE * TILE_ELEMS]; // 51.3 MB
__device__ __nv_bfloat16 g_Alo[(size_t)NTILE * TILE_ELEMS]; // 51.3 MB
__device__ __nv_bfloat16 g_Bhi[NREL * TILE_ELEMS];
__device__ __nv_bfloat16 g_Blo[NREL * TILE_ELEMS];

// ---------------------------------------------------------------------------
__device__ __forceinline__ uint32_t smem_u32(const void* p) {
    uint32_t a;
    asm("{ .reg .u64 t; cvta.to.shared.u64 t, %1; cvt.u32.u64 %0, t; }"
        : "=r"(a) : "l"(p));
    return a;
}

// ldmatrix XOR swizzle: 256 B/row; 16B chunk id XORed with (row&7) in low 3 bits.
__device__ __forceinline__ uint32_t swz_off(int r, int chunk) {
    return (uint32_t)(r * 256 + (((chunk & 8) | ((chunk ^ (r & 7)) & 7)) << 4));
}

#define LDSM_X4(r0, r1, r2, r3, addr) \
    asm volatile("ldmatrix.sync.aligned.m8n8.x4.shared.b16 {%0,%1,%2,%3}, [%4];" \
                 : "=r"(r0), "=r"(r1), "=r"(r2), "=r"(r3) : "r"(addr))

__device__ __forceinline__ void mma16816(float* c, const uint32_t* a, const uint32_t* b) {
    asm volatile("mma.sync.aligned.m16n8k16.row.col.f32.bf16.bf16.f32 "
                 "{%0,%1,%2,%3}, {%4,%5,%6,%7}, {%8,%9}, {%0,%1,%2,%3};"
                 : "+f"(c[0]), "+f"(c[1]), "+f"(c[2]), "+f"(c[3])
                 : "r"(a[0]), "r"(a[1]), "r"(a[2]), "r"(a[3]),
                   "r"(b[0]), "r"(b[1]));
}

#define CP_ASYNC16(sm, g) \
    asm volatile("cp.async.cg.shared.global [%0], [%1], 16;" :: "r"(sm), "l"(g))
#define CP_COMMIT() asm volatile("cp.async.commit_group;" ::: "memory")
#define CP_WAIT0()  asm volatile("cp.async.wait_group 0;" ::: "memory")

// ---------------------------------------------------------------------------
__global__ void zero_counts_kernel() {
    int i = blockIdx.x * blockDim.x + threadIdx.x;
    int stride = gridDim.x * blockDim.x;
    for (int j = i; j < TOTAL_DST_ROWS; j += stride) g_cnt[j] = 0;
    for (int j = i; j < NREL * MAXN; j += stride) g_outdeg[j] = 0;
}

// ---------------------------------------------------------------------------
__global__ void build_kernel(const int* __restrict__ s0, const int* __restrict__ d0,
                             const int* __restrict__ s1, const int* __restrict__ d1,
                             const int* __restrict__ s2, const int* __restrict__ d2,
                             const int* __restrict__ s3, const int* __restrict__ d3,
                             const int* __restrict__ s4, const int* __restrict__ d4,
                             const int* __restrict__ s5, const int* __restrict__ d5) {
    int i = blockIdx.x * blockDim.x + threadIdx.x;
    if (i >= NREL * NEDGE) return;
    int rel = i / NEDGE;
    int e = i - rel * NEDGE;
    const int* sp; const int* dp; int off;
    switch (rel) {
        case 0: sp = s0; dp = d0; off = 0;      break;
        case 1: sp = s1; dp = d1; off = 20000;  break;
        case 2: sp = s2; dp = d2; off = 30000;  break;
        case 3: sp = s3; dp = d3; off = 80000;  break;
        case 4: sp = s4; dp = d4; off = 130000; break;
        default: sp = s5; dp = d5; off = 180000; break;
    }
    int s = sp[e];
    int d = dp[e];
    atomicAdd(&g_outdeg[rel * MAXN + s], 1);
    int pos = atomicAdd(&g_cnt[off + d], 1);
    if (pos < CAP) g_bucket[(size_t)(off + d) * CAP + pos] = s;
}

// ---------------------------------------------------------------------------
// Precompute rsqrt(max(outdeg,1)) once — removes 39M in-loop MUFUs from gather.
__global__ void rsq_kernel() {
    int i = blockIdx.x * blockDim.x + threadIdx.x;
    if (i < NREL * MAXN)
        g_rsq[i] = rsqrtf(fmaxf((float)g_outdeg[i], 1.f));
}

// ---------------------------------------------------------------------------
// Pre-split W into K-major (B[n][k]) swizzled bf16 tiles.
// 16 blocks per relation (96 total): each block covers 1024 elements.
#define PREPW_BLOCKS_PER_REL 16
__global__ void prep_w_kernel(const float* __restrict__ W0, const float* __restrict__ W1,
                              const float* __restrict__ W2, const float* __restrict__ W3,
                              const float* __restrict__ W4, const float* __restrict__ W5) {
    int rel = blockIdx.x / PREPW_BLOCKS_PER_REL;
    int seg = blockIdx.x % PREPW_BLOCKS_PER_REL;
    const float* W;
    switch (rel) {
        case 0: W = W0; break; case 1: W = W1; break; case 2: W = W2; break;
        case 3: W = W3; break; case 4: W = W4; break; default: W = W5; break;
    }
    char* bh = (char*)(g_Bhi + (size_t)rel * TILE_ELEMS);
    char* bl = (char*)(g_Blo + (size_t)rel * TILE_ELEMS);
    const int base = seg * (D * D / PREPW_BLOCKS_PER_REL);   // 1024 per block
#pragma unroll
    for (int t = 0; t < D * D / PREPW_BLOCKS_PER_REL / 256; t++) {
        int idx = base + t * 256 + threadIdx.x;
        int k = idx >> 7, n = idx & 127;       // W[k][n] -> B[n][k]
        float v = W[idx];
        __nv_bfloat16 h = __float2bfloat16(v);
        __nv_bfloat16 l = __float2bfloat16(v - __bfloat162float(h));
        uint32_t p = swz_off(n, k >> 3) + (uint32_t)((k & 7) * 2);
        *(__nv_bfloat16*)(bh + p) = h;
        *(__nv_bfloat16*)(bl + p) = l;
    }
}

// ---------------------------------------------------------------------------
// Gather: warp per padded dst row; writes split-bf16 into swizzled tiles.
// Inner loop: ld src idx -> ld precomputed rsq -> ld.128 X -> 4 FMA.
__global__ void gather_all_kernel(const float* __restrict__ X0,  // svc  (sc)
                                  const float* __restrict__ X1,  // inst (in)
                                  const float* __restrict__ X2,  // node (ni)
                                  const float* __restrict__ X3,  // inst (ii)
                                  const float* __restrict__ X4,  // svc  (si)
                                  const float* __restrict__ X5)  // inst (is)
{
    int gw = (blockIdx.x * blockDim.x + threadIdx.x) >> 5;   // padded row id
    int lane = threadIdx.x & 31;
    int tile = gw >> 7;
    if (tile >= NTILE) return;

    int rel, pbase, segN, tbase; const float* X; float scale;
    if      (tile < 157)  { rel = 0; X = X0; scale = 0.5f;      pbase = 0;      segN = 20000; tbase = 0; }
    else if (tile < 236)  { rel = 1; X = X1; scale = 1.0f;      pbase = 20000;  segN = 10000; tbase = 157; }
    else if (tile < 627)  { rel = 2; X = X2; scale = 1.f / 3.f; pbase = 30000;  segN = 50000; tbase = 236; }
    else if (tile < 1018) { rel = 3; X = X3; scale = 1.f / 3.f; pbase = 80000;  segN = 50000; tbase = 627; }
    else if (tile < 1409) { rel = 4; X = X4; scale = 1.f / 3.f; pbase = 130000; segN = 50000; tbase = 1018; }
    else                  { rel = 5; X = X5; scale = 0.5f;      pbase = 180000; segN = 20000; tbase = 1409; }

    int local = gw - (tbase << 7);
    float4 acc = make_float4(0.f, 0.f, 0.f, 0.f);
    int cnt = 0;
    if (local < segN) {
        int g = pbase + local;
        cnt = g_cnt[g];
        int deg = cnt < CAP ? cnt : CAP;
        const int* bk = g_bucket + (size_t)g * CAP;
        const float* rq = g_rsq + rel * MAXN;
        const float4* Xv = (const float4*)X + lane;
        for (int j = 0; j < deg; j++) {
            int s = bk[j];
            float rs = __ldg(rq + s);
            float4 v = Xv[(size_t)s * 32];
            acc.x = fmaf(v.x, rs, acc.x);
            acc.y = fmaf(v.y, rs, acc.y);
            acc.z = fmaf(v.z, rs, acc.z);
            acc.w = fmaf(v.w, rs, acc.w);
        }
        float c = rsqrtf(fmaxf((float)cnt, 1.f)) * scale;
        acc.x *= c; acc.y *= c; acc.z *= c; acc.w *= c;
    }
    __nv_bfloat16 h0 = __float2bfloat16(acc.x);
    __nv_bfloat16 h1 = __float2bfloat16(acc.y);
    __nv_bfloat16 h2 = __float2bfloat16(acc.z);
    __nv_bfloat16 h3 = __float2bfloat16(acc.w);
    __nv_bfloat16 l0 = __float2bfloat16(acc.x - __bfloat162float(h0));
    __nv_bfloat16 l1 = __float2bfloat16(acc.y - __bfloat162float(h1));
    __nv_bfloat16 l2 = __float2bfloat16(acc.z - __bfloat162float(h2));
    __nv_bfloat16 l3 = __float2bfloat16(acc.w - __bfloat162float(h3));

    int r = gw & 127;
    uint32_t p = swz_off(r, lane >> 1) + (uint32_t)((lane & 1) * 8);
    char* bh = (char*)g_Ahi + (size_t)tile * TILE_ELEMS * 2 + p;
    char* bl = (char*)g_Alo + (size_t)tile * TILE_ELEMS * 2 + p;
    union { __nv_bfloat162 b2[2]; uint2 u; } uh, ul;
    uh.b2[0] = __halves2bfloat162(h0, h1); uh.b2[1] = __halves2bfloat162(h2, h3);
    ul.b2[0] = __halves2bfloat162(l0, l1); ul.b2[1] = __halves2bfloat162(l2, l3);
    *(uint2*)bh = uh.u;
    *(uint2*)bl = ul.u;
}

// ---------------------------------------------------------------------------
// HMMA GEMM: 128x128 output per block, 8 warps (4x2, warp tile 32x64), 256 thr.
// cp.async double-buffered A staging (race-free); B copied per chunk.
// 3 split products per relation chunk, fp32 register accumulators.
#define OFF_A0HI 0
#define OFF_A0LO 32768
#define OFF_A1HI 65536
#define OFF_A1LO 98304
#define OFF_BHI  131072
#define OFF_BLO  163840
#define SMEM_BYTES 196608

__device__ __forceinline__ void stage_a_async(uint32_t sb, int buf, int tile, int tid) {
    uint32_t shi = sb + (buf ? OFF_A1HI : OFF_A0HI);
    uint32_t slo = sb + (buf ? OFF_A1LO : OFF_A0LO);
    const char* gh = (const char*)g_Ahi + (size_t)tile * TILE_ELEMS * 2;
    const char* gl = (const char*)g_Alo + (size_t)tile * TILE_ELEMS * 2;
#pragma unroll
    for (int i = 0; i < 8; i++) {
        uint32_t off = (uint32_t)(tid + i * 256) * 16;
        CP_ASYNC16(shi + off, gh + off);
        CP_ASYNC16(slo + off, gl + off);
    }
}

// One K=128 pass: acc += A(sA) @ B(sB)^T.  (Validated mapping.)
__device__ __forceinline__ void mma_pass(uint32_t sA, uint32_t sB,
                                         float acc[2][8][4], int lane,
                                         int wm, int wn) {
#pragma unroll
    for (int ks = 0; ks < 8; ks++) {
        uint32_t a[2][4];
#pragma unroll
        for (int mt = 0; mt < 2; mt++) {
            int row = wm * 32 + mt * 16 + (lane & 15);
            int chunk = ks * 2 + (lane >> 4);
            LDSM_X4(a[mt][0], a[mt][1], a[mt][2], a[mt][3], sA + swz_off(row, chunk));
        }
        uint32_t bfr[8][2];
#pragma unroll
        for (int jp = 0; jp < 4; jp++) {
            int quarter = lane >> 3;
            int nrow = wn * 64 + (jp * 2 + (quarter >> 1)) * 8 + (lane & 7);
            int chunk = ks * 2 + (quarter & 1);
            LDSM_X4(bfr[jp * 2][0], bfr[jp * 2][1], bfr[jp * 2 + 1][0], bfr[jp * 2 + 1][1],
                    sB + swz_off(nrow, chunk));
        }
#pragma unroll
        for (int mt = 0; mt < 2; mt++)
#pragma unroll
            for (int nt = 0; nt < 8; nt++)
                mma16816(acc[mt][nt], a[mt], bfr[nt]);
    }
}

__global__ void __launch_bounds__(256, 1)
tc_gemm_kernel(const float* __restrict__ b_sc, const float* __restrict__ b_in,
               const float* __restrict__ b_ni, const float* __restrict__ b_ii,
               const float* __restrict__ b_si, const float* __restrict__ b_is,
               float* __restrict__ out) {
    extern __shared__ char smem[];
    uint32_t sb = smem_u32(smem);
    int tid = threadIdx.x, wid = tid >> 5, lane = tid & 31;
    int wm = wid >> 1, wn = wid & 1;
    int b = blockIdx.x;

    // Heavy blocks first: inst (nrel=3), svc (nrel=2), node (nrel=1).
    int nrel, bl, n_rows;
    int tiles[3]; int rels[3];
    const float* bias0; const float* bias1; const float* bias2;
    float scale; float* obase;
    if (b < 391) {
        bl = b; nrel = 3; n_rows = N_INST; scale = 1.f / 3.f;
        obase = out + (size_t)N_NODE * D;
        tiles[0] = 236 + bl; tiles[1] = 627 + bl; tiles[2] = 1018 + bl;
        rels[0] = 2; rels[1] = 3; rels[2] = 4;
        bias0 = b_ni; bias1 = b_ii; bias2 = b_si;
    } else if (b < 548) {
        bl = b - 391; nrel = 2; n_rows = N_SVC; scale = 0.5f;
        obase = out + (size_t)(N_NODE + N_INST) * D;
        tiles[0] = bl; tiles[1] = 1409 + bl;
        rels[0] = 0; rels[1] = 5;
        bias0 = b_sc; bias1 = b_is; bias2 = 0;
    } else {
        bl = b - 548; nrel = 1; n_rows = N_NODE; scale = 1.0f; obase = out;
        tiles[0] = 157 + bl; rels[0] = 1;
        bias0 = b_in; bias1 = 0; bias2 = 0;
    }
    int row0 = bl * 128;

    float acc[2][8][4];
#pragma unroll
    for (int i = 0; i < 2; i++)
#pragma unroll
        for (int j = 0; j < 8; j++)
#pragma unroll
            for (int k = 0; k < 4; k++) acc[i][j][k] = 0.f;

    // Prefetch A(0).
    stage_a_async(sb, 0, tiles[0], tid);
    CP_COMMIT();

    for (int r = 0; r < nrel; r++) {
        CP_WAIT0();                // A(r) landed (only one group in flight)
        __syncthreads();           // all warps done with previous chunk's compute

        // Now safe to prefetch A(r+1) into the buffer last read at chunk r-1.
        if (r + 1 < nrel) {
            stage_a_async(sb, (r + 1) & 1, tiles[r + 1], tid);
            CP_COMMIT();
        }

        // Copy B(r) from L2 (shared by all blocks of this dst type).
        {
            const uint4* gbh = (const uint4*)(g_Bhi + (size_t)rels[r] * TILE_ELEMS);
            const uint4* gbl = (const uint4*)(g_Blo + (size_t)rels[r] * TILE_ELEMS);
            uint4* dbh = (uint4*)(smem + OFF_BHI);
            uint4* dbl = (uint4*)(smem + OFF_BLO);
#pragma unroll
            for (int i = 0; i < 8; i++) {
                int idx = tid + i * 256;
                dbh[idx] = gbh[idx];
                dbl[idx] = gbl[idx];
            }
        }
        __syncthreads();

        uint32_t sAhi = sb + ((r & 1) ? OFF_A1HI : OFF_A0HI);
        uint32_t sAlo = sb + ((r & 1) ? OFF_A1LO : OFF_A0LO);
        mma_pass(sAhi, sb + OFF_BHI, acc, lane, wm, wn);  // hi*hi
        mma_pass(sAlo, sb + OFF_BHI, acc, lane, wm, wn);  // lo*hi
        mma_pass(sAhi, sb + OFF_BLO, acc, lane, wm, wn);  // hi*lo
    }

    // Epilogue: combined scaled bias + relu, direct float2 stores.
    float2 bb[8];
#pragma unroll
    for (int nt = 0; nt < 8; nt++) {
        int c = wn * 64 + nt * 8 + (lane & 3) * 2;
        float v0 = bias0[c], v1 = bias0[c + 1];
        if (nrel > 1) { v0 += bias1[c]; v1 += bias1[c + 1]; }
        if (nrel > 2) { v0 += bias2[c]; v1 += bias2[c + 1]; }
        bb[nt].x = v0 * scale;
        bb[nt].y = v1 * scale;
    }
#pragma unroll
    for (int mt = 0; mt < 2; mt++) {
        int rbase = row0 + wm * 32 + mt * 16 + (lane >> 2);
#pragma unroll
        for (int half = 0; half < 2; half++) {
            int grow = rbase + half * 8;
            if (grow >= n_rows) continue;
            float* orow = obase + (size_t)grow * D;
#pragma unroll
            for (int nt = 0; nt < 8; nt++) {
                int c = wn * 64 + nt * 8 + (lane & 3) * 2;
                float2 v;
                v.x = fmaxf(acc[mt][nt][half * 2 + 0] + bb[nt].x, 0.f);
                v.y = fmaxf(acc[mt][nt][half * 2 + 1] + bb[nt].y, 0.f);
                *(float2*)(orow + c) = v;
            }
        }
    }
}

// ---------------------------------------------------------------------------
extern "C" void kernel_launch(void* const* d_in, const int* in_sizes, int n_in,
                              void* d_out, int out_size) {
    const float* node_feat = (const float*)d_in[0];
    const float* inst_feat = (const float*)d_in[1];
    const float* svc_feat  = (const float*)d_in[2];

    const int*   e_src[NREL];
    const int*   e_dst[NREL];
    const float* W[NREL];
    const float* B[NREL];
    for (int r = 0; r < NREL; r++) {
        e_src[r] = (const int*)  d_in[3 + r * 4 + 0];
        e_dst[r] = (const int*)  d_in[3 + r * 4 + 1];
        W[r]     = (const float*)d_in[3 + r * 4 + 2];
        B[r]     = (const float*)d_in[3 + r * 4 + 3];
    }

    float* out = (float*)d_out;

    static bool attr_set = false;
    if (!attr_set) {
        cudaFuncSetAttribute(tc_gemm_kernel,
                             cudaFuncAttributeMaxDynamicSharedMemorySize, SMEM_BYTES);
        attr_set = true;
    }

    // 1. zero counts
    zero_counts_kernel<<<512, 256>>>();

    // 2. build buckets + out-degrees
    build_kernel<<<(NREL * NEDGE + 255) / 256, 256>>>(
        e_src[0], e_dst[0], e_src[1], e_dst[1], e_src[2], e_dst[2],
        e_src[3], e_dst[3], e_src[4], e_dst[4], e_src[5], e_dst[5]);

    // 3. precompute rsqrt(outdeg) + pre-split W tiles (96-way parallel)
    rsq_kernel<<<(NREL * MAXN + 255) / 256, 256>>>();
    prep_w_kernel<<<NREL * PREPW_BLOCKS_PER_REL, 256>>>(
        W[0], W[1], W[2], W[3], W[4], W[5]);

    // 4. gather -> split-bf16 swizzled A tiles
    gather_all_kernel<<<NTILE * 16, 256>>>(
        svc_feat, inst_feat, node_feat, inst_feat, svc_feat, inst_feat);

    // 5. tensor-core GEMM (627 blocks, heavy-first, pipelined A)
    tc_gemm_kernel<<<627, 256, SMEM_BYTES>>>(
        B[0], B[1], B[2], B[3], B[4], B[5], out);
}